// round 10
// baseline (speedup 1.0000x reference)
#include <cuda_runtime.h>
#include <math.h>
#include <stdint.h>

// Problem constants
#define Tt   512
#define Bb   64
#define Dd   256
#define Uu   512
#define Mm   64
#define NZt  2112   // 4*U + M

#define NUBLK 128   // u-blocks: 4 u-cols each (16 z-cols)
#define NEBLK 8     // e-blocks: 8 e-cols each
#define NBLK  136
#define NTHR  544   // 512 main threads + 1 gate warp
#define NTILES (33 * 512)

// ---------------- device scratch (free-running across graph replays) ----------------
__device__ float g_Z[(size_t)Tt * NZt * Bb];   // Z[t][n][b]
__device__ float g_hT[2][Bb][Uu];              // hidden state [b][u], double buffered
__device__ float g_ze[Bb][Mm];                 // pre-softmax e logits

struct __align__(128) Cnt { unsigned int v; unsigned int pad[31]; };
__device__ Cnt g_harr[8];    // per-chunk h arrival counters (+16*512 per replay)
__device__ Cnt g_earr;       // e arrivals (+8*512 per replay)
__device__ Cnt g_eepoch;     // e epoch word (value R*512 + t+1)
__device__ Cnt g_zdone;      // Z-phase barrier (+136 per replay)
__device__ Cnt g_tix;        // replay ticket counter (+136 per replay)

// SMEM float offsets (recurrence)
#define OFF_US   0              // u: [512k][16c]=8192 ; e: [512k][8c]=4096
#define OFF_CR   8192           // cring [64 slot][4 u][64 b] = 16384
#define OFF_H    24576          // 4 h buffers x [64 b][68] = 17408
#define OFF_ZT   41984          // zt [16 c][65] = 1040
#define OFF_PS   43024          // partial-sum buffer = 1040
#define OFF_ZES  44064          // softmax probs [64 b][65] = 4160
#define OFF_HST  48224          // h staging [4 uul][64 b] = 256
#define OFF_GF   48480          // 16 flag words (0-7: h chunks, 8: e epoch)
#define SMEM_F   48496          // 193984 bytes
// Z-phase scratch (overlaps US/CR region, used strictly before them)
#define OFF_XS0  0              // team0 x tile [64][65]
#define OFF_WS0  4160           // team0 W tile [64][64]
#define OFF_XS1  8256
#define OFF_WS1  12416          // end 16512 < 24576

// ---------------- PTX helpers ----------------
__device__ __forceinline__ void cp16(uint32_t dst, const float* src) {
    asm volatile("cp.async.cg.shared.global [%0], [%1], 16;" :: "r"(dst), "l"(src));
}
__device__ __forceinline__ void cp_commit() { asm volatile("cp.async.commit_group;"); }
__device__ __forceinline__ void cp_wait0()  { asm volatile("cp.async.wait_group 0;"); }
__device__ __forceinline__ unsigned ld_acq(const unsigned int* p) {
    unsigned v;
    asm volatile("ld.acquire.gpu.global.u32 %0, [%1];" : "=r"(v) : "l"(p));
    return v;
}
__device__ __forceinline__ void red_rel(unsigned int* p) {
    asm volatile("red.release.gpu.global.add.u32 [%0], 1;" :: "l"(p));
}
__device__ __forceinline__ void st_rel_g(unsigned int* p, unsigned v) {
    asm volatile("st.release.gpu.global.u32 [%0], %1;" :: "l"(p), "r"(v));
}
__device__ __forceinline__ unsigned ld_acq_sh(const unsigned int* p) {
    unsigned v, a = (unsigned)__cvta_generic_to_shared(p);
    asm volatile("ld.acquire.cta.shared.u32 %0, [%1];" : "=r"(v) : "r"(a));
    return v;
}
__device__ __forceinline__ void st_rel_sh(unsigned int* p, unsigned v) {
    unsigned a = (unsigned)__cvta_generic_to_shared(p);
    asm volatile("st.release.cta.shared.u32 [%0], %1;" :: "r"(a), "r"(v));
}
#define NBAR() asm volatile("bar.sync 1, 512;" ::: "memory")
#define TBAR(id) asm volatile("bar.sync %0, 256;" :: "r"(id) : "memory")

// packed fp32x2 FMA (FFMA2)
__device__ __forceinline__ unsigned long long pack2(float a, float b) {
    unsigned long long r;
    asm("mov.b64 %0, {%1, %2};" : "=l"(r) : "f"(a), "f"(b));
    return r;
}
__device__ __forceinline__ void fma2(unsigned long long& d,
                                     unsigned long long a, unsigned long long b) {
    asm("fma.rn.f32x2 %0, %1, %2, %0;" : "+l"(d) : "l"(a), "l"(b));
}
__device__ __forceinline__ void unpack2(unsigned long long v, float& a, float& b) {
    asm("mov.b64 {%0, %1}, %2;" : "=f"(a), "=f"(b) : "l"(v));
}

// ================= single fused kernel =================
__global__ __launch_bounds__(NTHR, 1) void xlstm_kernel(
    float* __restrict__ out, const float* __restrict__ x,
    const float* __restrict__ Wi, const float* __restrict__ Wf,
    const float* __restrict__ Wo, const float* __restrict__ Wc,
    const float* __restrict__ We,
    const float* __restrict__ bi, const float* __restrict__ bf,
    const float* __restrict__ bo, const float* __restrict__ bc,
    const float* __restrict__ be,
    const float* __restrict__ Ui, const float* __restrict__ Uf,
    const float* __restrict__ Uo, const float* __restrict__ Uc,
    const float* __restrict__ Ue)
{
    extern __shared__ float sm[];
    float* cr  = sm + OFF_CR;
    float* Us  = sm + OFF_US;
    float* zt  = sm + OFF_ZT;
    float* ps  = sm + OFF_PS;
    float* zes = sm + OFF_ZES;
    float* hst = sm + OFF_HST;
    unsigned int* gf = (unsigned int*)(sm + OFF_GF);
    __shared__ unsigned sR;

    const uint32_t smem_u = (uint32_t)__cvta_generic_to_shared(sm);
    const int bid = blockIdx.x;
    const int tid = threadIdx.x;
    const bool isE = (bid >= NUBLK);

    // ---- replay ticket: R = replay index (graph replays serialize) ----
    if (tid == 0) {
        unsigned old = atomicAdd(&g_tix.v, 1u);
        sR = old / (unsigned)NBLK;
    }
    if (tid < 16) gf[tid] = 0u;
    __syncthreads();                 // ALL 544 threads, exactly once
    const unsigned R = sR;

    // ======== gate warp (tids 512..543) ========
    if (tid >= 512) {
        const int lane = tid - 512;
        if (lane < 8) {
            const unsigned base = R * (16u * 512u);
            for (int t = 1; t < Tt; t++) {
                while (ld_acq(&g_harr[lane].v) < base + 16u * (unsigned)t) { }
                st_rel_sh(&gf[lane], (unsigned)t);
            }
        } else if (lane == 8 && !isE) {
            const unsigned base = R * 512u;
            for (int t = 0; t < Tt; t++) {
                while (ld_acq(&g_eepoch.v) < base + (unsigned)(t + 1)) { }
                st_rel_sh(&gf[8], (unsigned)(t + 1));
            }
        }
        return;
    }

    // ================= PHASE A: precompute Z =================
    {
        const int team = tid >> 8;            // 0/1
        const int ttid = tid & 255;
        float* xs = sm + (team ? OFF_XS1 : OFF_XS0);
        float* Ws = sm + (team ? OFF_WS1 : OFF_WS0);
        const int barid = 2 + team;
        const int ptx = ttid & 15, pty = ttid >> 4;

        for (int tile = bid * 2 + team; tile < NTILES; tile += NBLK * 2) {
            const int t  = tile / 33;
            const int nt = tile % 33;
            const float* W; const float* bv;
            switch (nt >> 3) {
                case 0:  W = Wi; bv = bi; break;
                case 1:  W = Wf; bv = bf; break;
                case 2:  W = Wo; bv = bo; break;
                case 3:  W = Wc; bv = bc; break;
                default: W = We; bv = be; break;
            }
            const int stride = (nt < 32) ? Uu : Mm;
            const int col0   = (nt & 7) * 64;

            unsigned long long acc01[4], acc23[4];
            {
                unsigned long long p01 = pack2(bv[col0 + ptx * 4 + 0], bv[col0 + ptx * 4 + 1]);
                unsigned long long p23 = pack2(bv[col0 + ptx * 4 + 2], bv[col0 + ptx * 4 + 3]);
                #pragma unroll
                for (int i = 0; i < 4; i++) { acc01[i] = p01; acc23[i] = p23; }
            }
            for (int kb = 0; kb < 4; kb++) {
                TBAR(barid);
                #pragma unroll
                for (int l = 0; l < 16; l++) {
                    int idx = l * 256 + ttid;
                    int b = idx >> 6, kk = idx & 63;
                    xs[b * 65 + kk] = x[(size_t)b * Tt * Dd + (size_t)t * Dd + kb * 64 + kk];
                }
                #pragma unroll
                for (int l = 0; l < 16; l++) {
                    int idx = l * 256 + ttid;
                    int kk = idx >> 6, nn = idx & 63;
                    Ws[kk * 64 + nn] = W[(size_t)(kb * 64 + kk) * stride + col0 + nn];
                }
                TBAR(barid);
                #pragma unroll 16
                for (int kk = 0; kk < 64; kk++) {
                    ulonglong2 wv = *reinterpret_cast<const ulonglong2*>(&Ws[kk * 64 + ptx * 4]);
                    #pragma unroll
                    for (int i = 0; i < 4; i++) {
                        float xv = xs[(pty * 4 + i) * 65 + kk];
                        unsigned long long xx = pack2(xv, xv);
                        fma2(acc01[i], xx, wv.x);
                        fma2(acc23[i], xx, wv.y);
                    }
                }
            }
            float a[4][4];
            #pragma unroll
            for (int i = 0; i < 4; i++) {
                unpack2(acc01[i], a[i][0], a[i][1]);
                unpack2(acc23[i], a[i][2], a[i][3]);
            }
            #pragma unroll
            for (int j = 0; j < 4; j++) {
                int n = nt * 64 + ptx * 4 + j;
                float4 v = make_float4(a[0][j], a[1][j], a[2][j], a[3][j]);
                *reinterpret_cast<float4*>(&g_Z[((size_t)t * NZt + n) * Bb + pty * 4]) = v;
            }
        }
    }
    NBAR();
    if (tid == 0) {
        red_rel(&g_zdone.v);
        while (ld_acq(&g_zdone.v) < (R + 1u) * (unsigned)NBLK) { }
    }
    NBAR();

    // ================= load persistent U slice =================
    if (!isE) {
        const int u0 = bid * 4;
        const int tc = tid & 15;
        const float* Ug;
        switch (tc >> 2) {
            case 0:  Ug = Ui; break;
            case 1:  Ug = Uf; break;
            case 2:  Ug = Uo; break;
            default: Ug = Uc; break;
        }
        const int lc = u0 + (tc & 3);
        for (int k = tid >> 4; k < Uu; k += 32)
            Us[k * 16 + tc] = Ug[(size_t)k * Uu + lc];
    } else {
        const int m0 = (bid - NUBLK) * 8;
        const int tc = tid & 7;
        for (int k = tid >> 3; k < Uu; k += 64)
            Us[k * 8 + tc] = Ue[(size_t)k * Mm + m0 + tc];
    }
    NBAR();

    // ================= PHASE B: recurrence =================
    const int half = tid >> 8;
    const int tx   = tid & 3;
    const int ty   = (tid >> 2) & 63;
    const int b3   = bid & 3;
    float* const hbufs = sm + OFF_H + half * 2 * 4352;
    const uint32_t hdst0 = smem_u + (uint32_t)(OFF_H + (half * 2 + 0) * 4352 + ty * 68 + tx * 16) * 4;
    const uint32_t hdst1 = smem_u + (uint32_t)(OFF_H + (half * 2 + 1) * 4352 + ty * 68 + tx * 16) * 4;

    for (int t = 0; t < Tt; t++) {
        const float* hsrc = &g_hT[t & 1][0][0];

        if (!isE) {
            const int u0 = bid * 4;

            float zl0 = 0.f, zl1 = 0.f, zl2 = 0.f, zl3 = 0.f;
            if (half == 0) {
                const float* zp = &g_Z[((size_t)t * NZt + tx * Uu + u0) * Bb + ty];
                zl0 = __ldcs(zp);
                zl1 = __ldcs(zp + 64);
                zl2 = __ldcs(zp + 128);
                zl3 = __ldcs(zp + 192);
            }

            unsigned long long acc01 = 0ull, acc23 = 0ull;
            if (t > 0) {
                // prologue: gate chunk b3, prefetch
                {
                    int lrr = b3;
                    while (ld_acq_sh(&gf[half * 4 + lrr]) < (unsigned)t) { }
                    const float* s = hsrc + (size_t)ty * Uu + half * 256 + lrr * 64 + tx * 16;
                    #pragma unroll
                    for (int j = 0; j < 4; j++) cp16(hdst0 + j * 16, s + j * 4);
                    cp_commit();
                }
                for (int r = 0; r < 4; r++) {
                    cp_wait0();
                    NBAR();
                    if (r < 3) {
                        int lrr = (b3 + r + 1) & 3;
                        while (ld_acq_sh(&gf[half * 4 + lrr]) < (unsigned)t) { }
                        const float* s = hsrc + (size_t)ty * Uu + half * 256 + lrr * 64 + tx * 16;
                        uint32_t d = ((r & 1) == 0) ? hdst1 : hdst0;
                        #pragma unroll
                        for (int j = 0; j < 4; j++) cp16(d + j * 16, s + j * 4);
                        cp_commit();
                    }
                    const float* hp = hbufs + (r & 1) * 4352 + ty * 68;
                    const float* Ub = &Us[(half * 256 + ((b3 + r) & 3) * 64) * 16 + tx * 4];
                    #pragma unroll
                    for (int kk = 0; kk < 64; kk += 2) {
                        float2 hv = *reinterpret_cast<const float2*>(&hp[kk]);
                        ulonglong2 ua = *reinterpret_cast<const ulonglong2*>(&Ub[kk * 16]);
                        ulonglong2 ub = *reinterpret_cast<const ulonglong2*>(&Ub[kk * 16 + 16]);
                        fma2(acc01, pack2(hv.x, hv.x), ua.x);
                        fma2(acc23, pack2(hv.x, hv.x), ua.y);
                        fma2(acc01, pack2(hv.y, hv.y), ub.x);
                        fma2(acc23, pack2(hv.y, hv.y), ub.y);
                    }
                }
            }

            // epilogue: combine halves + Z; wait e-epoch flag
            {
                float a0, a1, a2, a3;
                unpack2(acc01, a0, a1);
                unpack2(acc23, a2, a3);
                if (half == 1) {
                    ps[(tx * 4 + 0) * 65 + ty] = a0;
                    ps[(tx * 4 + 1) * 65 + ty] = a1;
                    ps[(tx * 4 + 2) * 65 + ty] = a2;
                    ps[(tx * 4 + 3) * 65 + ty] = a3;
                }
                while (ld_acq_sh(&gf[8]) < (unsigned)(t + 1)) { }
                NBAR();
                if (half == 0) {
                    zt[(tx * 4 + 0) * 65 + ty] = a0 + ps[(tx * 4 + 0) * 65 + ty] + zl0;
                    zt[(tx * 4 + 1) * 65 + ty] = a1 + ps[(tx * 4 + 1) * 65 + ty] + zl1;
                    zt[(tx * 4 + 2) * 65 + ty] = a2 + ps[(tx * 4 + 2) * 65 + ty] + zl2;
                    zt[(tx * 4 + 3) * 65 + ty] = a3 + ps[(tx * 4 + 3) * 65 + ty] + zl3;
                }
            }

            // softmax: 8 lanes per batch row, direct from L2
            {
                const int sb = tid >> 3, sq = tid & 7;
                const float4* zrow = reinterpret_cast<const float4*>(&g_ze[sb][sq * 8]);
                float4 v0 = __ldcg(zrow);
                float4 v1 = __ldcg(zrow + 1);
                float v[8] = {v0.x, v0.y, v0.z, v0.w, v1.x, v1.y, v1.z, v1.w};
                float mx = -1e30f;
                #pragma unroll
                for (int i = 0; i < 8; i++) mx = fmaxf(mx, v[i]);
                mx = fmaxf(mx, __shfl_xor_sync(0xffffffffu, mx, 1));
                mx = fmaxf(mx, __shfl_xor_sync(0xffffffffu, mx, 2));
                mx = fmaxf(mx, __shfl_xor_sync(0xffffffffu, mx, 4));
                float s = 0.f;
                #pragma unroll
                for (int i = 0; i < 8; i++) { v[i] = __expf(v[i] - mx); s += v[i]; }
                s += __shfl_xor_sync(0xffffffffu, s, 1);
                s += __shfl_xor_sync(0xffffffffu, s, 2);
                s += __shfl_xor_sync(0xffffffffu, s, 4);
                float inv = 1.0f / s;
                #pragma unroll
                for (int i = 0; i < 8; i++) zes[sb * 65 + sq * 8 + i] = v[i] * inv;
            }
            NBAR();

            // phase 2: memory read (m split across halves) + update
            const int item = tid & 255;
            {
                const int uul = item >> 6, b = item & 63;
                const int mlim = (t < 64) ? t : 64;
                const int lo = half * 32;
                const int hi = (mlim < lo + 32) ? mlim : lo + 32;
                float p = 0.f;
                const float* zr = &zes[b * 65];
                #pragma unroll 4
                for (int m = lo; m < hi; m++)
                    p += zr[m] * cr[(((t - 1 - m) & 63) * 4 + uul) * 64 + b];
                if (half == 1) ps[item] = p;
                NBAR();
                if (half == 0) {
                    float mc = p + ps[item];
                    float iv = zt[(uul)      * 65 + b];
                    float fv = zt[(4 + uul)  * 65 + b];
                    float ov = zt[(8 + uul)  * 65 + b];
                    float cv = zt[(12 + uul) * 65 + b];
                    iv = 1.0f / (1.0f + __expf(-iv));
                    fv = 1.0f / (1.0f + __expf(-fv));
                    ov = 1.0f / (1.0f + __expf(-ov));
                    cv = tanhf(cv);
                    float c = fv * mc + iv * cv;
                    float h = ov * tanhf(c);
                    cr[((t & 63) * 4 + uul) * 64 + b] = c;
                    hst[uul * 64 + b] = h;
                }
            }
            NBAR();
            if (tid < 64) {
                const int b = tid;
                float4 hv = make_float4(hst[b], hst[64 + b], hst[128 + b], hst[192 + b]);
                *reinterpret_cast<float4*>(&g_hT[(t + 1) & 1][b][u0]) = hv;
                *reinterpret_cast<float4*>(&out[((size_t)b * Tt + t) * Uu + u0]) = hv;
            }
            NBAR();
            if (tid == 0) red_rel(&g_harr[bid >> 4].v);
        } else {
            // ---- e-block: ze GEMM (8 cols, split-K, rotated chunks) ----
            const int m0 = (bid - NUBLK) * 8;
            const int c0 = tx * 2;
            float zl0 = 0.f, zl1 = 0.f;
            if (half == 0) {
                zl0 = __ldcs(&g_Z[((size_t)t * NZt + 4 * Uu + m0 + c0) * Bb + ty]);
                zl1 = __ldcs(&g_Z[((size_t)t * NZt + 4 * Uu + m0 + c0 + 1) * Bb + ty]);
            }
            unsigned long long accE = 0ull;
            if (t > 0) {
                {
                    int lrr = b3;
                    while (ld_acq_sh(&gf[half * 4 + lrr]) < (unsigned)t) { }
                    const float* s = hsrc + (size_t)ty * Uu + half * 256 + lrr * 64 + tx * 16;
                    #pragma unroll
                    for (int j = 0; j < 4; j++) cp16(hdst0 + j * 16, s + j * 4);
                    cp_commit();
                }
                for (int r = 0; r < 4; r++) {
                    cp_wait0();
                    NBAR();
                    if (r < 3) {
                        int lrr = (b3 + r + 1) & 3;
                        while (ld_acq_sh(&gf[half * 4 + lrr]) < (unsigned)t) { }
                        const float* s = hsrc + (size_t)ty * Uu + half * 256 + lrr * 64 + tx * 16;
                        uint32_t d = ((r & 1) == 0) ? hdst1 : hdst0;
                        #pragma unroll
                        for (int j = 0; j < 4; j++) cp16(d + j * 16, s + j * 4);
                        cp_commit();
                    }
                    const float* hp = hbufs + (r & 1) * 4352 + ty * 68;
                    const float* Up = &Us[(half * 256 + ((b3 + r) & 3) * 64) * 8 + c0];
                    #pragma unroll
                    for (int kk = 0; kk < 64; kk += 2) {
                        float2 hv = *reinterpret_cast<const float2*>(&hp[kk]);
                        unsigned long long u0v = *reinterpret_cast<const unsigned long long*>(&Up[kk * 8]);
                        unsigned long long u1v = *reinterpret_cast<const unsigned long long*>(&Up[(kk + 1) * 8]);
                        fma2(accE, pack2(hv.x, hv.x), u0v);
                        fma2(accE, pack2(hv.y, hv.y), u1v);
                    }
                }
            }
            float a0, a1;
            unpack2(accE, a0, a1);
            const int item = tid & 255;
            if (half == 1) { ps[item * 2] = a0; ps[item * 2 + 1] = a1; }
            NBAR();
            if (half == 0) {
                g_ze[ty][m0 + c0]     = a0 + ps[item * 2]     + zl0;
                g_ze[ty][m0 + c0 + 1] = a1 + ps[item * 2 + 1] + zl1;
            }
            NBAR();
            if (tid == 0) {
                red_rel(&g_earr.v);
                if (bid == NUBLK) {
                    unsigned ebase = R * (8u * 512u);
                    while (ld_acq(&g_earr.v) < ebase + 8u * (unsigned)(t + 1)) { }
                    st_rel_g(&g_eepoch.v, R * 512u + (unsigned)(t + 1));
                }
            }
        }
    }
}

// ---------------- launch: ONE kernel ----------------
extern "C" void kernel_launch(void* const* d_in, const int* in_sizes, int n_in,
                              void* d_out, int out_size) {
    (void)in_sizes; (void)n_in; (void)out_size;
    const float* x  = (const float*)d_in[0];
    const float* Wi = (const float*)d_in[1];
    const float* Ui = (const float*)d_in[2];
    const float* bi = (const float*)d_in[3];
    const float* Wf = (const float*)d_in[4];
    const float* Uf = (const float*)d_in[5];
    const float* bf = (const float*)d_in[6];
    const float* Wo = (const float*)d_in[7];
    const float* Uo = (const float*)d_in[8];
    const float* bo = (const float*)d_in[9];
    const float* Wc = (const float*)d_in[10];
    const float* Uc = (const float*)d_in[11];
    const float* bc = (const float*)d_in[12];
    const float* We = (const float*)d_in[13];
    const float* Ue = (const float*)d_in[14];
    const float* be = (const float*)d_in[15];
    float* out = (float*)d_out;

    const size_t SMEM = (size_t)SMEM_F * sizeof(float);   // 193984 B
    cudaFuncSetAttribute(xlstm_kernel, cudaFuncAttributeMaxDynamicSharedMemorySize, (int)SMEM);

    xlstm_kernel<<<NBLK, NTHR, SMEM>>>(out, x,
        Wi, Wf, Wo, Wc, We, bi, bf, bo, bc, be,
        Ui, Uf, Uo, Uc, Ue);
}

// round 11
// speedup vs baseline: 1.0439x; 1.0439x over previous
#include <cuda_runtime.h>
#include <math.h>
#include <stdint.h>

// Problem constants
#define Tt   512
#define Bb   64
#define Dd   256
#define Uu   512
#define Mm   64
#define NZt  2112   // 4*U + M

#define NUBLK 128   // u-blocks: 4 u-cols each (16 z-cols)
#define NEBLK 8     // e-blocks: 8 e-cols each
#define NBLK  136
#define NTHR  544   // 512 main threads + 1 gate warp
#define NTILES (33 * 512)

// ---------------- device scratch (free-running across graph replays) ----------------
__device__ float g_Z[(size_t)Tt * NZt * Bb];   // Z[t][n][b]
__device__ float g_hTT[2][Uu][Bb];             // hidden state TRANSPOSED [u][b], double buffered
__device__ float g_ze[Bb][Mm];                 // pre-softmax e logits

struct __align__(128) Cnt { unsigned int v; unsigned int pad[31]; };
__device__ Cnt g_harr;       // h arrivals (+128*512 per replay)
__device__ Cnt g_earr;       // e arrivals (+8*512 per replay)
__device__ Cnt g_zdone;      // Z-phase barrier (+136 per replay)
__device__ Cnt g_tix;        // replay ticket counter (+136 per replay)

// SMEM float offsets
#define OFF_UD   0            // U duplicated [512 k][32] = 16384
#define OFF_CR   16384        // cring [64 slot][4 u][64 b] = 16384
#define OFF_HT   32768        // hT [512 k][36] = 18432  (ps2 reduction buffer aliases here)
#define OFF_ZT   51200        // zt [16 c][65] = 1040
#define OFF_ZES  52240        // softmax probs [64 b][65] = 4160
#define OFF_HST  56400        // h staging [4 uul][64 b] = 256
#define OFF_PSB  56656        // phase2 partial buffer [256]
#define OFF_GF   56912        // flags: 0=h ready t, 1=e ready t+1
#define SMEM_F   56928        // 227712 bytes
// Z-phase scratch (overlaps UD/CR region, used strictly before them)
#define OFF_XS0  0
#define OFF_WS0  4160
#define OFF_XS1  8256
#define OFF_WS1  12416        // end 16512

// ---------------- PTX helpers ----------------
__device__ __forceinline__ void cp16(uint32_t dst, const float* src) {
    asm volatile("cp.async.cg.shared.global [%0], [%1], 16;" :: "r"(dst), "l"(src));
}
__device__ __forceinline__ void cp_commit() { asm volatile("cp.async.commit_group;"); }
__device__ __forceinline__ void cp_wait0()  { asm volatile("cp.async.wait_group 0;"); }
__device__ __forceinline__ unsigned ld_acq(const unsigned int* p) {
    unsigned v;
    asm volatile("ld.acquire.gpu.global.u32 %0, [%1];" : "=r"(v) : "l"(p));
    return v;
}
__device__ __forceinline__ void red_rel(unsigned int* p) {
    asm volatile("red.release.gpu.global.add.u32 [%0], 1;" :: "l"(p));
}
__device__ __forceinline__ unsigned ld_acq_sh(const unsigned int* p) {
    unsigned v, a = (unsigned)__cvta_generic_to_shared(p);
    asm volatile("ld.acquire.cta.shared.u32 %0, [%1];" : "=r"(v) : "r"(a));
    return v;
}
__device__ __forceinline__ void st_rel_sh(unsigned int* p, unsigned v) {
    unsigned a = (unsigned)__cvta_generic_to_shared(p);
    asm volatile("st.release.cta.shared.u32 [%0], %1;" :: "r"(a), "r"(v));
}
#define NBAR() asm volatile("bar.sync 1, 512;" ::: "memory")
#define TBAR(id) asm volatile("bar.sync %0, 256;" :: "r"(id) : "memory")

// packed fp32x2 FMA (FFMA2)
__device__ __forceinline__ unsigned long long pack2(float a, float b) {
    unsigned long long r;
    asm("mov.b64 %0, {%1, %2};" : "=l"(r) : "f"(a), "f"(b));
    return r;
}
__device__ __forceinline__ void fma2(unsigned long long& d,
                                     unsigned long long a, unsigned long long b) {
    asm("fma.rn.f32x2 %0, %1, %2, %0;" : "+l"(d) : "l"(a), "l"(b));
}
__device__ __forceinline__ void unpack2(unsigned long long v, float& a, float& b) {
    asm("mov.b64 {%0, %1}, %2;" : "=f"(a), "=f"(b) : "l"(v));
}

// ================= single fused kernel =================
__global__ __launch_bounds__(NTHR, 1) void xlstm_kernel(
    float* __restrict__ out, const float* __restrict__ x,
    const float* __restrict__ Wi, const float* __restrict__ Wf,
    const float* __restrict__ Wo, const float* __restrict__ Wc,
    const float* __restrict__ We,
    const float* __restrict__ bi, const float* __restrict__ bf,
    const float* __restrict__ bo, const float* __restrict__ bc,
    const float* __restrict__ be,
    const float* __restrict__ Ui, const float* __restrict__ Uf,
    const float* __restrict__ Uo, const float* __restrict__ Uc,
    const float* __restrict__ Ue)
{
    extern __shared__ float sm[];
    float* Ud  = sm + OFF_UD;
    float* cr  = sm + OFF_CR;
    float* hT  = sm + OFF_HT;
    float* ps2 = sm + OFF_HT;          // alias: used only between compute and next fill
    float* zt  = sm + OFF_ZT;
    float* zes = sm + OFF_ZES;
    float* hst = sm + OFF_HST;
    float* psb = sm + OFF_PSB;
    unsigned int* gf = (unsigned int*)(sm + OFF_GF);
    __shared__ unsigned sR;

    const uint32_t smem_u = (uint32_t)__cvta_generic_to_shared(sm);
    const int bid = blockIdx.x;
    const int tid = threadIdx.x;
    const bool isE = (bid >= NUBLK);

    if (tid == 0) {
        unsigned old = atomicAdd(&g_tix.v, 1u);
        sR = old / (unsigned)NBLK;
    }
    if (tid < 16) gf[tid] = 0u;
    __syncthreads();
    const unsigned R = sR;

    // ======== gate warp (tids 512..543) ========
    if (tid >= 512) {
        const int lane = tid - 512;
        if (lane == 0) {
            const unsigned base = R * (128u * 512u);
            for (int t = 1; t < Tt; t++) {
                while (ld_acq(&g_harr.v) < base + 128u * (unsigned)t) { }
                st_rel_sh(&gf[0], (unsigned)t);
            }
        } else if (lane == 1 && !isE) {
            const unsigned base = R * (8u * 512u);
            for (int t = 0; t < Tt; t++) {
                while (ld_acq(&g_earr.v) < base + 8u * (unsigned)(t + 1)) { }
                st_rel_sh(&gf[1], (unsigned)(t + 1));
            }
        }
        return;
    }

    // ================= PHASE A: precompute Z =================
    {
        const int team = tid >> 8;
        const int ttid = tid & 255;
        float* xs = sm + (team ? OFF_XS1 : OFF_XS0);
        float* Ws = sm + (team ? OFF_WS1 : OFF_WS0);
        const int barid = 2 + team;
        const int ptx = ttid & 15, pty = ttid >> 4;

        for (int tile = bid * 2 + team; tile < NTILES; tile += NBLK * 2) {
            const int t  = tile / 33;
            const int nt = tile % 33;
            const float* W; const float* bv;
            switch (nt >> 3) {
                case 0:  W = Wi; bv = bi; break;
                case 1:  W = Wf; bv = bf; break;
                case 2:  W = Wo; bv = bo; break;
                case 3:  W = Wc; bv = bc; break;
                default: W = We; bv = be; break;
            }
            const int stride = (nt < 32) ? Uu : Mm;
            const int col0   = (nt & 7) * 64;

            unsigned long long acc01[4], acc23[4];
            {
                unsigned long long p01 = pack2(bv[col0 + ptx * 4 + 0], bv[col0 + ptx * 4 + 1]);
                unsigned long long p23 = pack2(bv[col0 + ptx * 4 + 2], bv[col0 + ptx * 4 + 3]);
                #pragma unroll
                for (int i = 0; i < 4; i++) { acc01[i] = p01; acc23[i] = p23; }
            }
            for (int kb = 0; kb < 4; kb++) {
                TBAR(barid);
                #pragma unroll
                for (int l = 0; l < 16; l++) {
                    int idx = l * 256 + ttid;
                    int b = idx >> 6, kk = idx & 63;
                    xs[b * 65 + kk] = x[(size_t)b * Tt * Dd + (size_t)t * Dd + kb * 64 + kk];
                }
                #pragma unroll
                for (int l = 0; l < 16; l++) {
                    int idx = l * 256 + ttid;
                    int kk = idx >> 6, nn = idx & 63;
                    Ws[kk * 64 + nn] = W[(size_t)(kb * 64 + kk) * stride + col0 + nn];
                }
                TBAR(barid);
                #pragma unroll 16
                for (int kk = 0; kk < 64; kk++) {
                    ulonglong2 wv = *reinterpret_cast<const ulonglong2*>(&Ws[kk * 64 + ptx * 4]);
                    #pragma unroll
                    for (int i = 0; i < 4; i++) {
                        float xv = xs[(pty * 4 + i) * 65 + kk];
                        unsigned long long xx = pack2(xv, xv);
                        fma2(acc01[i], xx, wv.x);
                        fma2(acc23[i], xx, wv.y);
                    }
                }
            }
            float a[4][4];
            #pragma unroll
            for (int i = 0; i < 4; i++) {
                unpack2(acc01[i], a[i][0], a[i][1]);
                unpack2(acc23[i], a[i][2], a[i][3]);
            }
            #pragma unroll
            for (int j = 0; j < 4; j++) {
                int n = nt * 64 + ptx * 4 + j;
                float4 v = make_float4(a[0][j], a[1][j], a[2][j], a[3][j]);
                *reinterpret_cast<float4*>(&g_Z[((size_t)t * NZt + n) * Bb + pty * 4]) = v;
            }
        }
    }
    NBAR();
    if (tid == 0) {
        red_rel(&g_zdone.v);
        while (ld_acq(&g_zdone.v) < (R + 1u) * (unsigned)NBLK) { }
    }
    NBAR();

    // ================= load duplicated U slice (once) =================
    const int u0 = bid * 4;
    const int m0 = (bid - NUBLK) * 8;
    {
        const int c = tid & 15, kk0 = tid >> 4;
        if (!isE) {
            const float* Ug;
            switch (c >> 2) {
                case 0:  Ug = Ui; break;
                case 1:  Ug = Uf; break;
                case 2:  Ug = Uo; break;
                default: Ug = Uc; break;
            }
            const int lc = u0 + (c & 3);
            for (int k = kk0; k < Uu; k += 32) {
                float v = Ug[(size_t)k * Uu + lc];
                Ud[k * 32 + c * 2] = v;
                Ud[k * 32 + c * 2 + 1] = v;
            }
        } else {
            for (int k = kk0; k < Uu; k += 32) {
                float v = (c < 8) ? Ue[(size_t)k * Mm + m0 + c] : 0.f;
                Ud[k * 32 + c * 2] = v;
                Ud[k * 32 + c * 2 + 1] = v;
            }
        }
    }
    NBAR();

    // ================= PHASE B: recurrence =================
    // GEMM map: slice s = tid>>5 (16 slices x 32k), lane: bgrp 0..7, cgrp 0..3
    const int s    = tid >> 5;
    const int lidw = tid & 31;
    const int bgrp = lidw & 7, cgrp = lidw >> 3;
    const int kbase = s * 32;
    // reduce map: c = tid>>5 (0..15), bl = tid&31
    const int rc = tid >> 5, rb = tid & 31;
    // phase2 map
    const int p2h = tid >> 8;            // m-half
    const int item = tid & 255;
    // fill dst (row tid)
    const uint32_t fdst = smem_u + (uint32_t)(OFF_HT + tid * 36) * 4;

    // Z column for reduce lane
    int zcol; bool zvalid;
    if (!isE) { zcol = (rc >> 2) * Uu + u0 + (rc & 3); zvalid = true; }
    else      { zvalid = (rc < 8); zcol = 4 * Uu + m0 + (zvalid ? rc : 0); }

    for (int t = 0; t < Tt; t++) {
        // Z prefetch (both b-halves)
        float z0 = 0.f, z1 = 0.f;
        if (zvalid) {
            const float* zp = &g_Z[((size_t)t * NZt + zcol) * Bb];
            z0 = __ldcs(zp + rb);
            z1 = __ldcs(zp + 32 + rb);
        }

        if (t > 0) {
            // h gate
            if (tid == 0) { while (ld_acq_sh(&gf[0]) < (unsigned)t) { } }
            NBAR();

            const float* hsrc = &g_hTT[t & 1][0][0];   // [512 u][64 b]

            #pragma unroll
            for (int bh = 0; bh < 2; bh++) {
                // ---- fill hT[k][b] for this b-half (coalesced cp.async) ----
                {
                    const float* src = hsrc + (size_t)tid * Bb + bh * 32;
                    #pragma unroll
                    for (int j = 0; j < 8; j++) cp16(fdst + j * 16, src + j * 4);
                    cp_commit();
                    cp_wait0();
                }
                NBAR();

                // ---- compute: 4b x 4c tile over 32 k ----
                unsigned long long acc[2][4];
                #pragma unroll
                for (int i = 0; i < 2; i++)
                    #pragma unroll
                    for (int j = 0; j < 4; j++) acc[i][j] = 0ull;

                const float* hp = &hT[kbase * 36 + bgrp * 4];
                const float* up = &Ud[kbase * 32 + cgrp * 8];
                #pragma unroll 8
                for (int k = 0; k < 32; k++) {
                    ulonglong2 hv  = *reinterpret_cast<const ulonglong2*>(hp + k * 36);
                    ulonglong2 u01 = *reinterpret_cast<const ulonglong2*>(up + k * 32);
                    ulonglong2 u23 = *reinterpret_cast<const ulonglong2*>(up + k * 32 + 4);
                    fma2(acc[0][0], hv.x, u01.x);
                    fma2(acc[0][1], hv.x, u01.y);
                    fma2(acc[0][2], hv.x, u23.x);
                    fma2(acc[0][3], hv.x, u23.y);
                    fma2(acc[1][0], hv.y, u01.x);
                    fma2(acc[1][1], hv.y, u01.y);
                    fma2(acc[1][2], hv.y, u23.x);
                    fma2(acc[1][3], hv.y, u23.y);
                }
                NBAR();                       // hT reads done -> ps2 alias safe

                // ---- stage split-K partials: ps2[s][c][b36] ----
                #pragma unroll
                for (int j = 0; j < 4; j++) {
                    const int base = (s * 16 + cgrp * 4 + j) * 36 + bgrp * 4;
                    *reinterpret_cast<unsigned long long*>(&ps2[base])     = acc[0][j];
                    *reinterpret_cast<unsigned long long*>(&ps2[base + 2]) = acc[1][j];
                }
                NBAR();

                // ---- reduce 16 slices + Z ----
                {
                    float v = 0.f;
                    #pragma unroll
                    for (int s2 = 0; s2 < 16; s2++)
                        v += ps2[(s2 * 16 + rc) * 36 + rb];
                    float zz = bh ? z1 : z0;
                    if (!isE)
                        zt[rc * 65 + bh * 32 + rb] = v + zz;
                    else if (zvalid)
                        g_ze[bh * 32 + rb][m0 + rc] = v + zz;
                }
                NBAR();                       // ps2 reads done -> next fill safe
            }
        } else {
            // t == 0: h = 0, z = Z only
            if (!isE) {
                zt[rc * 65 + rb]      = z0;
                zt[rc * 65 + 32 + rb] = z1;
            } else if (zvalid) {
                g_ze[rb][m0 + rc]      = z0;
                g_ze[32 + rb][m0 + rc] = z1;
            }
            NBAR();
        }

        if (isE) {
            asm volatile("membar.gl;" ::: "memory");
            NBAR();
            if (tid == 0) red_rel(&g_earr.v);
            continue;
        }

        // ---- u-blocks: wait e logits ----
        if (tid == 0) { while (ld_acq_sh(&gf[1]) < (unsigned)(t + 1)) { } }
        NBAR();

        // ---- softmax: 8 lanes per batch row, direct from L2 ----
        {
            const int sb = tid >> 3, sq = tid & 7;
            const float4* zrow = reinterpret_cast<const float4*>(&g_ze[sb][sq * 8]);
            float4 v0 = __ldcg(zrow);
            float4 v1 = __ldcg(zrow + 1);
            float v[8] = {v0.x, v0.y, v0.z, v0.w, v1.x, v1.y, v1.z, v1.w};
            float mx = -1e30f;
            #pragma unroll
            for (int i = 0; i < 8; i++) mx = fmaxf(mx, v[i]);
            mx = fmaxf(mx, __shfl_xor_sync(0xffffffffu, mx, 1));
            mx = fmaxf(mx, __shfl_xor_sync(0xffffffffu, mx, 2));
            mx = fmaxf(mx, __shfl_xor_sync(0xffffffffu, mx, 4));
            float sum = 0.f;
            #pragma unroll
            for (int i = 0; i < 8; i++) { v[i] = __expf(v[i] - mx); sum += v[i]; }
            sum += __shfl_xor_sync(0xffffffffu, sum, 1);
            sum += __shfl_xor_sync(0xffffffffu, sum, 2);
            sum += __shfl_xor_sync(0xffffffffu, sum, 4);
            float inv = 1.0f / sum;
            #pragma unroll
            for (int i = 0; i < 8; i++) zes[sb * 65 + sq * 8 + i] = v[i] * inv;
        }
        NBAR();

        // ---- phase 2: memory read (m split across halves) + update ----
        {
            const int uul = item >> 6, b = item & 63;
            const int mlim = (t < 64) ? t : 64;
            const int lo = p2h * 32;
            const int hi = (mlim < lo + 32) ? mlim : lo + 32;
            float p = 0.f;
            const float* zr = &zes[b * 65];
            #pragma unroll 4
            for (int m = lo; m < hi; m++)
                p += zr[m] * cr[(((t - 1 - m) & 63) * 4 + uul) * 64 + b];
            if (p2h == 1) psb[item] = p;
            NBAR();
            if (p2h == 0) {
                float mc = p + psb[item];
                float iv = zt[(uul)      * 65 + b];
                float fv = zt[(4 + uul)  * 65 + b];
                float ov = zt[(8 + uul)  * 65 + b];
                float cv = zt[(12 + uul) * 65 + b];
                iv = 1.0f / (1.0f + __expf(-iv));
                fv = 1.0f / (1.0f + __expf(-fv));
                ov = 1.0f / (1.0f + __expf(-ov));
                cv = tanhf(cv);
                float c = fv * mc + iv * cv;
                float h = ov * tanhf(c);
                cr[((t & 63) * 4 + uul) * 64 + b] = c;
                hst[uul * 64 + b] = h;
            }
        }
        NBAR();
        // ---- stores: out (by b) + transposed h (by u row) ----
        if (tid < 64) {
            const int b = tid;
            float4 hv = make_float4(hst[b], hst[64 + b], hst[128 + b], hst[192 + b]);
            *reinterpret_cast<float4*>(&out[((size_t)b * Tt + t) * Uu + u0]) = hv;
        } else if (tid < 128) {
            const int r = tid - 64, uul = r >> 4, seg = r & 15;
            float4 hv = *reinterpret_cast<const float4*>(&hst[uul * 64 + seg * 4]);
            *reinterpret_cast<float4*>(&g_hTT[(t + 1) & 1][u0 + uul][seg * 4]) = hv;
        }
        NBAR();
        if (tid == 0) red_rel(&g_harr.v);
    }
}

// ---------------- launch: ONE kernel ----------------
extern "C" void kernel_launch(void* const* d_in, const int* in_sizes, int n_in,
                              void* d_out, int out_size) {
    (void)in_sizes; (void)n_in; (void)out_size;
    const float* x  = (const float*)d_in[0];
    const float* Wi = (const float*)d_in[1];
    const float* Ui = (const float*)d_in[2];
    const float* bi = (const float*)d_in[3];
    const float* Wf = (const float*)d_in[4];
    const float* Uf = (const float*)d_in[5];
    const float* bf = (const float*)d_in[6];
    const float* Wo = (const float*)d_in[7];
    const float* Uo = (const float*)d_in[8];
    const float* bo = (const float*)d_in[9];
    const float* Wc = (const float*)d_in[10];
    const float* Uc = (const float*)d_in[11];
    const float* bc = (const float*)d_in[12];
    const float* We = (const float*)d_in[13];
    const float* Ue = (const float*)d_in[14];
    const float* be = (const float*)d_in[15];
    float* out = (float*)d_out;

    const size_t SMEM = (size_t)SMEM_F * sizeof(float);   // 227712 B
    cudaFuncSetAttribute(xlstm_kernel, cudaFuncAttributeMaxDynamicSharedMemorySize, (int)SMEM);

    xlstm_kernel<<<NBLK, NTHR, SMEM>>>(out, x,
        Wi, Wf, Wo, Wc, We, bi, bf, bo, bc, be,
        Ui, Uf, Uo, Uc, Ue);
}